// round 7
// baseline (speedup 1.0000x reference)
#include <cuda_runtime.h>
#include <cuda_bf16.h>
#include <math.h>
#include <stdint.h>

#define B_    4
#define T_    2048
#define H_    16
#define D_    128
#define ATTN_ 2048
#define BT_   (B_*T_)

// ---------------------------------------------------------------------------
// Scratch (__device__ globals). Weights concat: rows 0-6143 = wq|wk|wv, 6144+ = wo.
// ---------------------------------------------------------------------------
__device__ __nv_bfloat16 g_xh[(size_t)BT_ * ATTN_];
__device__ __nv_bfloat16 g_xl[(size_t)BT_ * ATTN_];
__device__ __nv_bfloat16 g_qh[(size_t)BT_ * ATTN_];
__device__ __nv_bfloat16 g_ql[(size_t)BT_ * ATTN_];
__device__ __nv_bfloat16 g_kh[(size_t)BT_ * ATTN_];
__device__ __nv_bfloat16 g_kl[(size_t)BT_ * ATTN_];
__device__ __nv_bfloat16 g_vh[(size_t)BT_ * ATTN_];
__device__ __nv_bfloat16 g_vl[(size_t)BT_ * ATTN_];
__device__ __nv_bfloat16 g_yh[(size_t)BT_ * ATTN_];
__device__ __nv_bfloat16 g_yl[(size_t)BT_ * ATTN_];
__device__ __nv_bfloat16 g_wh[(size_t)4 * ATTN_ * ATTN_];
__device__ __nv_bfloat16 g_wl[(size_t)4 * ATTN_ * ATTN_];
__device__ float g_cosT[T_ * 64];
__device__ float g_sinT[T_ * 64];

// ---------------------------------------------------------------------------
// PTX helpers
// ---------------------------------------------------------------------------
__device__ __forceinline__ uint32_t smem_u32(const void* p) {
    uint32_t a;
    asm("{ .reg .u64 t; cvta.to.shared.u64 t, %1; cvt.u32.u64 %0, t; }" : "=r"(a) : "l"(p));
    return a;
}

#define CP_ASYNC16(dst, src) \
    asm volatile("cp.async.cg.shared.global [%0], [%1], 16;" :: "r"(dst), "l"(src))
#define CP_COMMIT() asm volatile("cp.async.commit_group;" ::: "memory")
#define CP_WAIT(n)  asm volatile("cp.async.wait_group %0;" :: "n"(n) : "memory")

__device__ __forceinline__ void ldsm4(uint32_t* r, uint32_t addr) {
    asm volatile("ldmatrix.sync.aligned.m8n8.x4.shared.b16 {%0,%1,%2,%3}, [%4];"
                 : "=r"(r[0]), "=r"(r[1]), "=r"(r[2]), "=r"(r[3]) : "r"(addr));
}
__device__ __forceinline__ void ldsm4t(uint32_t* r, uint32_t addr) {
    asm volatile("ldmatrix.sync.aligned.m8n8.x4.trans.shared.b16 {%0,%1,%2,%3}, [%4];"
                 : "=r"(r[0]), "=r"(r[1]), "=r"(r[2]), "=r"(r[3]) : "r"(addr));
}

__device__ __forceinline__ void mma16816(float* c, const uint32_t* a,
                                         uint32_t b0, uint32_t b1) {
    asm volatile(
        "mma.sync.aligned.m16n8k16.row.col.f32.bf16.bf16.f32 "
        "{%0,%1,%2,%3}, {%4,%5,%6,%7}, {%8,%9}, {%0,%1,%2,%3};"
        : "+f"(c[0]), "+f"(c[1]), "+f"(c[2]), "+f"(c[3])
        : "r"(a[0]), "r"(a[1]), "r"(a[2]), "r"(a[3]), "r"(b0), "r"(b1));
}

__device__ __forceinline__ uint32_t packbf2(float a, float b) {
    __nv_bfloat162 t = __halves2bfloat162(__float2bfloat16(a), __float2bfloat16(b));
    return *(uint32_t*)&t;
}

// ---------------------------------------------------------------------------
// Elementwise kernels
// ---------------------------------------------------------------------------
__global__ void rope_table_kernel(float* __restrict__ cosT, float* __restrict__ sinT) {
    const int t = blockIdx.x;
    const int i = threadIdx.x;
    const float kFreq = 0.07195578415606394f;  // ln(10000)/128
    const float inv = expf((float)(2 * i) * -kFreq);
    const float ang = (float)t * inv;
    float s, c;
    sincosf(ang, &s, &c);
    cosT[t * 64 + i] = c;
    sinT[t * 64 + i] = s;
}

__global__ void split_kernel(const float4* __restrict__ src,
                             __nv_bfloat162* __restrict__ hi,
                             __nv_bfloat162* __restrict__ lo, int n4) {
    int i = blockIdx.x * blockDim.x + threadIdx.x;
    if (i >= n4) return;
    float4 v = src[i];
    __nv_bfloat16 h0 = __float2bfloat16(v.x);
    __nv_bfloat16 h1 = __float2bfloat16(v.y);
    __nv_bfloat16 h2 = __float2bfloat16(v.z);
    __nv_bfloat16 h3 = __float2bfloat16(v.w);
    hi[2 * i]     = __halves2bfloat162(h0, h1);
    hi[2 * i + 1] = __halves2bfloat162(h2, h3);
    lo[2 * i]     = __halves2bfloat162(__float2bfloat16(v.x - __bfloat162float(h0)),
                                       __float2bfloat16(v.y - __bfloat162float(h1)));
    lo[2 * i + 1] = __halves2bfloat162(__float2bfloat16(v.z - __bfloat162float(h2)),
                                       __float2bfloat16(v.w - __bfloat162float(h3)));
}

__global__ void split_w_kernel(const float* __restrict__ w0, const float* __restrict__ w1,
                               const float* __restrict__ w2, const float* __restrict__ w3,
                               __nv_bfloat162* __restrict__ hi, __nv_bfloat162* __restrict__ lo,
                               int n4) {
    int i = blockIdx.x * blockDim.x + threadIdx.x;
    if (i >= n4) return;
    const int z = blockIdx.z;
    const float* src = (z == 0) ? w0 : (z == 1) ? w1 : (z == 2) ? w2 : w3;
    float4 v = ((const float4*)src)[i];
    const size_t off = (size_t)z * n4 * 2;
    __nv_bfloat16 h0 = __float2bfloat16(v.x);
    __nv_bfloat16 h1 = __float2bfloat16(v.y);
    __nv_bfloat16 h2 = __float2bfloat16(v.z);
    __nv_bfloat16 h3 = __float2bfloat16(v.w);
    hi[off + 2 * i]     = __halves2bfloat162(h0, h1);
    hi[off + 2 * i + 1] = __halves2bfloat162(h2, h3);
    lo[off + 2 * i]     = __halves2bfloat162(__float2bfloat16(v.x - __bfloat162float(h0)),
                                             __float2bfloat16(v.y - __bfloat162float(h1)));
    lo[off + 2 * i + 1] = __halves2bfloat162(__float2bfloat16(v.z - __bfloat162float(h2)),
                                             __float2bfloat16(v.w - __bfloat162float(h3)));
}

// ---------------------------------------------------------------------------
// GEMM v3: CTA 128x256, 512 threads = 16 warps (2 M x 8 N), warp tile 64x32.
// BK=64, 2-stage. acc = 64 regs/thread -> ~115 total, 4 warps/SMSP.
// ---------------------------------------------------------------------------
static constexpr int GBM = 128, GBN = 256, GBK = 64;
static constexpr int LDS_ = 72;
static constexpr int A_B  = 128 * LDS_ * 2;      // 18432
static constexpr int W_B  = 256 * LDS_ * 2;      // 36864
static constexpr int STAGE_B = 2 * A_B + 2 * W_B;   // 110592
static constexpr int GEMM_SMEM = 2 * STAGE_B;       // 221184
static constexpr int GTHREADS = 512;

struct GemmCore {
    __device__ static __forceinline__ void run(
        uint32_t sBase, float (&acc)[4][4][4],
        const __nv_bfloat16* gAh, const __nv_bfloat16* gAl,
        const __nv_bfloat16* gWh, const __nv_bfloat16* gWl,
        int tid, int wm, int wn, int lr, int lc)
    {
        const int cc = tid & 7;        // 16B chunk within 128B row
        const int rb = tid >> 3;       // 0..63
        const int NIT = ATTN_ / GBK;

        auto load_stage = [&](uint32_t st, int k0) {
#pragma unroll
            for (int bb = 0; bb < 2; bb++) {
                const int r = bb * 64 + rb;
                const uint32_t so = r * (LDS_ * 2) + cc * 16;
                const size_t go = (size_t)r * ATTN_ + k0 + cc * 8;
                CP_ASYNC16(st + so, gAh + go);
                CP_ASYNC16(st + A_B + so, gAl + go);
            }
#pragma unroll
            for (int bb = 0; bb < 4; bb++) {
                const int r = bb * 64 + rb;
                const uint32_t so = r * (LDS_ * 2) + cc * 16;
                const size_t go = (size_t)r * ATTN_ + k0 + cc * 8;
                CP_ASYNC16(st + 2 * A_B + so, gWh + go);
                CP_ASYNC16(st + 2 * A_B + W_B + so, gWl + go);
            }
            CP_COMMIT();
        };

        load_stage(sBase, 0);

        for (int kt = 0; kt < NIT; kt++) {
            if (kt + 1 < NIT) {
                load_stage(sBase + ((kt + 1) & 1) * STAGE_B, (kt + 1) * GBK);
                CP_WAIT(1);
            } else {
                CP_WAIT(0);
            }
            __syncthreads();

            const uint32_t st  = sBase + (kt & 1) * STAGE_B;
            const uint32_t sAh = st;
            const uint32_t sAl = st + A_B;
            const uint32_t sWh = st + 2 * A_B;
            const uint32_t sWl = st + 2 * A_B + W_B;

#pragma unroll
            for (int ks = 0; ks < 4; ks++) {
                const int kc = ks * 16 + lc;
                uint32_t ah[4][4], whf[2][4], wlf[2][4];
#pragma unroll
                for (int mt = 0; mt < 4; mt++)
                    ldsm4(ah[mt], sAh + ((wm + mt * 16 + lr) * LDS_ + kc) * 2);
#pragma unroll
                for (int g = 0; g < 2; g++)
                    ldsm4(whf[g], sWh + ((wn + g * 16 + lr) * LDS_ + kc) * 2);
#pragma unroll
                for (int g = 0; g < 2; g++)
                    ldsm4(wlf[g], sWl + ((wn + g * 16 + lr) * LDS_ + kc) * 2);

                // Ah * Wh
#pragma unroll
                for (int mt = 0; mt < 4; mt++)
#pragma unroll
                    for (int nt = 0; nt < 4; nt++)
                        mma16816(acc[mt][nt], ah[mt], whf[nt >> 1][nt & 1], whf[nt >> 1][(nt & 1) + 2]);
                // Ah * Wl
#pragma unroll
                for (int mt = 0; mt < 4; mt++)
#pragma unroll
                    for (int nt = 0; nt < 4; nt++)
                        mma16816(acc[mt][nt], ah[mt], wlf[nt >> 1][nt & 1], wlf[nt >> 1][(nt & 1) + 2]);
                // Al * Wh (reload A frags)
#pragma unroll
                for (int mt = 0; mt < 4; mt++)
                    ldsm4(ah[mt], sAl + ((wm + mt * 16 + lr) * LDS_ + kc) * 2);
#pragma unroll
                for (int mt = 0; mt < 4; mt++)
#pragma unroll
                    for (int nt = 0; nt < 4; nt++)
                        mma16816(acc[mt][nt], ah[mt], whf[nt >> 1][nt & 1], whf[nt >> 1][(nt & 1) + 2]);
            }
            __syncthreads();
        }
    }
};

// ---------------------------------------------------------------------------
// Fused QKV projection GEMM. grid (24, 64). blockIdx.x>>3 : 0=Q,1=K,2=V.
// ---------------------------------------------------------------------------
__global__ void __launch_bounds__(GTHREADS, 1) qkv_gemm(
    const __nv_bfloat16* __restrict__ Xh, const __nv_bfloat16* __restrict__ Xl,
    const __nv_bfloat16* __restrict__ Wh, const __nv_bfloat16* __restrict__ Wl,
    const float* __restrict__ bq, const float* __restrict__ bk, const float* __restrict__ bv,
    __nv_bfloat16* __restrict__ QH, __nv_bfloat16* __restrict__ QL,
    __nv_bfloat16* __restrict__ KH, __nv_bfloat16* __restrict__ KL,
    __nv_bfloat16* __restrict__ VH, __nv_bfloat16* __restrict__ VL,
    const float* __restrict__ cosT, const float* __restrict__ sinT)
{
    extern __shared__ char dsm[];
    const uint32_t sBase = smem_u32(dsm);

    const int tid  = threadIdx.x;
    const int wid  = tid >> 5;
    const int lane = tid & 31;
    const int wm   = (wid >> 3) * 64;   // 2 warp-rows
    const int wn   = (wid & 7) * 32;    // 8 warp-cols
    const int bm   = blockIdx.y * GBM;
    const int qkv  = blockIdx.x >> 3;
    const int bnl  = (blockIdx.x & 7) * GBN;
    const int bng  = blockIdx.x * GBN;

    float acc[4][4][4];
#pragma unroll
    for (int mt = 0; mt < 4; mt++)
#pragma unroll
        for (int nt = 0; nt < 4; nt++)
#pragma unroll
            for (int e = 0; e < 4; e++) acc[mt][nt][e] = 0.f;

    GemmCore::run(sBase, acc,
                  Xh + (size_t)bm * ATTN_, Xl + (size_t)bm * ATTN_,
                  Wh + (size_t)bng * ATTN_, Wl + (size_t)bng * ATTN_,
                  tid, wm, wn, lane & 15, (lane >> 4) << 3);

    const float* bias = (qkv == 0) ? bq : (qkv == 1) ? bk : bv;
    __nv_bfloat16* CH = (qkv == 0) ? QH : (qkv == 1) ? KH : VH;
    __nv_bfloat16* CL = (qkv == 0) ? QL : (qkv == 1) ? KL : VL;
    const bool rope  = (qkv != 2);
    const bool scale = (qkv == 0);
    const float qscale = 0.08838834764831843f;

    const int rr = lane >> 2;
    const int nn = (lane & 3) * 2;
#pragma unroll
    for (int mt = 0; mt < 4; mt++) {
#pragma unroll
        for (int half = 0; half < 2; half++) {
            const int m = bm + wm + mt * 16 + rr + half * 8;
            const int pos = m & (T_ - 1);
#pragma unroll
            for (int nt = 0; nt < 4; nt++) {
                const int n0 = bnl + wn + nt * 8 + nn;
                float v0 = acc[mt][nt][half * 2 + 0] + __ldg(&bias[n0]);
                float v1 = acc[mt][nt][half * 2 + 1] + __ldg(&bias[n0 + 1]);
                if (rope) {
                    const int pi = (n0 & (D_ - 1)) >> 1;
                    const float cv = __ldg(&cosT[pos * 64 + pi]);
                    const float sv = __ldg(&sinT[pos * 64 + pi]);
                    const float t1 = v0, t2 = v1;
                    v0 = t1 * cv - t2 * sv;
                    v1 = t1 * sv + t2 * cv;
                }
                if (scale) { v0 *= qscale; v1 *= qscale; }
                const __nv_bfloat16 h0 = __float2bfloat16(v0);
                const __nv_bfloat16 h1 = __float2bfloat16(v1);
                *(__nv_bfloat162*)(CH + (size_t)m * ATTN_ + n0) = __halves2bfloat162(h0, h1);
                *(__nv_bfloat162*)(CL + (size_t)m * ATTN_ + n0) = __halves2bfloat162(
                    __float2bfloat16(v0 - __bfloat162float(h0)),
                    __float2bfloat16(v1 - __bfloat162float(h1)));
            }
        }
    }
}

// ---------------------------------------------------------------------------
// Output projection GEMM: fp32 out + bias.
// ---------------------------------------------------------------------------
__global__ void __launch_bounds__(GTHREADS, 1) out_gemm(
    const __nv_bfloat16* __restrict__ Ah, const __nv_bfloat16* __restrict__ Al,
    const __nv_bfloat16* __restrict__ Wh, const __nv_bfloat16* __restrict__ Wl,
    const float* __restrict__ bias, float* __restrict__ Cf)
{
    extern __shared__ char dsm[];
    const uint32_t sBase = smem_u32(dsm);

    const int tid  = threadIdx.x;
    const int wid  = tid >> 5;
    const int lane = tid & 31;
    const int wm   = (wid >> 3) * 64;
    const int wn   = (wid & 7) * 32;
    const int bm   = blockIdx.y * GBM;
    const int bn   = blockIdx.x * GBN;

    float acc[4][4][4];
#pragma unroll
    for (int mt = 0; mt < 4; mt++)
#pragma unroll
        for (int nt = 0; nt < 4; nt++)
#pragma unroll
            for (int e = 0; e < 4; e++) acc[mt][nt][e] = 0.f;

    GemmCore::run(sBase, acc,
                  Ah + (size_t)bm * ATTN_, Al + (size_t)bm * ATTN_,
                  Wh + (size_t)bn * ATTN_, Wl + (size_t)bn * ATTN_,
                  tid, wm, wn, lane & 15, (lane >> 4) << 3);

    const int rr = lane >> 2;
    const int nn = (lane & 3) * 2;
#pragma unroll
    for (int mt = 0; mt < 4; mt++) {
#pragma unroll
        for (int half = 0; half < 2; half++) {
            const int m = bm + wm + mt * 16 + rr + half * 8;
#pragma unroll
            for (int nt = 0; nt < 4; nt++) {
                const int n0 = bn + wn + nt * 8 + nn;
                const float v0 = acc[mt][nt][half * 2 + 0] + __ldg(&bias[n0]);
                const float v1 = acc[mt][nt][half * 2 + 1] + __ldg(&bias[n0 + 1]);
                *(float2*)(Cf + (size_t)m * ATTN_ + n0) = make_float2(v0, v1);
            }
        }
    }
}

// ---------------------------------------------------------------------------
// Tensor-core causal flash attention (unchanged, passing).
// ---------------------------------------------------------------------------
static constexpr int FLD = 136;
static constexpr int FQB = 128 * FLD * 2;
static constexpr int FKB = 64 * FLD * 2;
static constexpr int FSTG = 4 * FKB;
static constexpr int FSMEM = 2 * FQB + 2 * FSTG;

__global__ void __launch_bounds__(256, 1) flash_mma(
    const __nv_bfloat16* __restrict__ Qh, const __nv_bfloat16* __restrict__ Ql,
    const __nv_bfloat16* __restrict__ Kh, const __nv_bfloat16* __restrict__ Kl,
    const __nv_bfloat16* __restrict__ Vh, const __nv_bfloat16* __restrict__ Vl,
    __nv_bfloat16* __restrict__ Yh, __nv_bfloat16* __restrict__ Yl)
{
    extern __shared__ char fsm[];
    const uint32_t sb  = smem_u32(fsm);
    const uint32_t sQH = sb;
    const uint32_t sQL = sb + FQB;
    const uint32_t sKV = sb + 2 * FQB;

    const int qt = blockIdx.x, h = blockIdx.y, b = blockIdx.z;
    const int tid = threadIdx.x, wid = tid >> 5, lane = tid & 31;
    const int wm = wid * 16;
    const int lr = lane & 15;
    const int lcg = (lane >> 4) << 3;

    const int ccf = tid & 15;
    const int r0f = tid >> 4;

    {
        const __nv_bfloat16* qh_g = Qh + ((size_t)(b * T_ + qt * 128)) * ATTN_ + h * D_;
        const __nv_bfloat16* ql_g = Ql + ((size_t)(b * T_ + qt * 128)) * ATTN_ + h * D_;
#pragma unroll
        for (int bb = 0; bb < 8; bb++) {
            const int r = bb * 16 + r0f;
            const uint32_t so = r * (FLD * 2) + ccf * 16;
            const size_t go = (size_t)r * ATTN_ + ccf * 8;
            CP_ASYNC16(sQH + so, qh_g + go);
            CP_ASYNC16(sQL + so, ql_g + go);
        }
        CP_COMMIT();
    }

    const int nkv = 2 * qt + 2;

    auto issue_kv = [&](int j) {
        const uint32_t st = sKV + (j & 1) * FSTG;
        const size_t base = ((size_t)(b * T_ + j * 64)) * ATTN_ + h * D_;
#pragma unroll
        for (int bb = 0; bb < 4; bb++) {
            const int r = bb * 16 + r0f;
            const uint32_t so = r * (FLD * 2) + ccf * 16;
            const size_t go = base + (size_t)r * ATTN_ + ccf * 8;
            CP_ASYNC16(st + so, Kh + go);
            CP_ASYNC16(st + FKB + so, Kl + go);
            CP_ASYNC16(st + 2 * FKB + so, Vh + go);
            CP_ASYNC16(st + 3 * FKB + so, Vl + go);
        }
        CP_COMMIT();
    };

    issue_kv(0);

    float Oacc[16][4];
#pragma unroll
    for (int nt = 0; nt < 16; nt++)
#pragma unroll
        for (int e = 0; e < 4; e++) Oacc[nt][e] = 0.f;
    float m0 = -1e30f, m1 = -1e30f, l0 = 0.f, l1 = 0.f;

    const int grow0 = qt * 128 + wm + (lane >> 2);
    const int grow1 = grow0 + 8;

    for (int j = 0; j < nkv; j++) {
        if (j + 1 < nkv) {
            issue_kv(j + 1);
            CP_WAIT(1);
        } else {
            CP_WAIT(0);
        }
        __syncthreads();

        const uint32_t st  = sKV + (j & 1) * FSTG;
        const uint32_t cKH = st;
        const uint32_t cKL = st + FKB;
        const uint32_t cVH = st + 2 * FKB;
        const uint32_t cVL = st + 3 * FKB;

        float sc[8][4];
#pragma unroll
        for (int nt = 0; nt < 8; nt++)
#pragma unroll
            for (int e = 0; e < 4; e++) sc[nt][e] = 0.f;

#pragma unroll 2
        for (int ks = 0; ks < 8; ks++) {
            const int kc = ks * 16 + lcg;
            uint32_t aQh[4], aQl[4], kh[4][4], kl[4][4];
            ldsm4(aQh, sQH + ((wm + lr) * FLD + kc) * 2);
            ldsm4(aQl, sQL + ((wm + lr) * FLD + kc) * 2);
#pragma unroll
            for (int g = 0; g < 4; g++) {
                ldsm4(kh[g], cKH + ((g * 16 + lr) * FLD + kc) * 2);
                ldsm4(kl[g], cKL + ((g * 16 + lr) * FLD + kc) * 2);
            }
#pragma unroll
            for (int nt = 0; nt < 8; nt++) {
                const uint32_t b0h = kh[nt >> 1][nt & 1], b1h = kh[nt >> 1][(nt & 1) + 2];
                mma16816(sc[nt], aQh, b0h, b1h);
                mma16816(sc[nt], aQh, kl[nt >> 1][nt & 1], kl[nt >> 1][(nt & 1) + 2]);
                mma16816(sc[nt], aQl, b0h, b1h);
            }
        }

        if (j >= 2 * qt) {
            const int c0 = j * 64 + ((lane & 3) << 1);
#pragma unroll
            for (int nt = 0; nt < 8; nt++) {
                const int gc = c0 + nt * 8;
                if (gc > grow0)     sc[nt][0] = -1e30f;
                if (gc + 1 > grow0) sc[nt][1] = -1e30f;
                if (gc > grow1)     sc[nt][2] = -1e30f;
                if (gc + 1 > grow1) sc[nt][3] = -1e30f;
            }
        }
        float mx0 = -1e30f, mx1 = -1e30f;
#pragma unroll
        for (int nt = 0; nt < 8; nt++) {
            mx0 = fmaxf(mx0, fmaxf(sc[nt][0], sc[nt][1]));
            mx1 = fmaxf(mx1, fmaxf(sc[nt][2], sc[nt][3]));
        }
        mx0 = fmaxf(mx0, __shfl_xor_sync(0xffffffffu, mx0, 1));
        mx0 = fmaxf(mx0, __shfl_xor_sync(0xffffffffu, mx0, 2));
        mx1 = fmaxf(mx1, __shfl_xor_sync(0xffffffffu, mx1, 1));
        mx1 = fmaxf(mx1, __shfl_xor_sync(0xffffffffu, mx1, 2));
        const float mn0 = fmaxf(m0, mx0), mn1 = fmaxf(m1, mx1);
        const float al0 = __expf(m0 - mn0), al1 = __expf(m1 - mn1);
        float ls0 = 0.f, ls1 = 0.f;
#pragma unroll
        for (int nt = 0; nt < 8; nt++) {
            sc[nt][0] = __expf(sc[nt][0] - mn0);
            sc[nt][1] = __expf(sc[nt][1] - mn0);
            sc[nt][2] = __expf(sc[nt][2] - mn1);
            sc[nt][3] = __expf(sc[nt][3] - mn1);
            ls0 += sc[nt][0] + sc[nt][1];
            ls1 += sc[nt][2] + sc[nt][3];
        }
        ls0 += __shfl_xor_sync(0xffffffffu, ls0, 1);
        ls0 += __shfl_xor_sync(0xffffffffu, ls0, 2);
        ls1 += __shfl_xor_sync(0xffffffffu, ls1, 1);
        ls1 += __shfl_xor_sync(0xffffffffu, ls1, 2);
        l0 = l0 * al0 + ls0; m0 = mn0;
        l1 = l1 * al1 + ls1; m1 = mn1;
#pragma unroll
        for (int nt = 0; nt < 16; nt++) {
            Oacc[nt][0] *= al0; Oacc[nt][1] *= al0;
            Oacc[nt][2] *= al1; Oacc[nt][3] *= al1;
        }

#pragma unroll
        for (int ks = 0; ks < 4; ks++) {
            uint32_t aPh[4], aPl[4];
            {
                const float p0 = sc[2 * ks][0],     p1 = sc[2 * ks][1];
                const float p2 = sc[2 * ks][2],     p3 = sc[2 * ks][3];
                const float p4 = sc[2 * ks + 1][0], p5 = sc[2 * ks + 1][1];
                const float p6 = sc[2 * ks + 1][2], p7 = sc[2 * ks + 1][3];
                aPh[0] = packbf2(p0, p1);
                aPh[1] = packbf2(p2, p3);
                aPh[2] = packbf2(p4, p5);
                aPh[3] = packbf2(p6, p7);
                aPl[0] = packbf2(p0 - __bfloat162float(__float2bfloat16(p0)),
                                 p1 - __bfloat162float(__float2bfloat16(p1)));
                aPl[1] = packbf2(p2 - __bfloat162float(__float2bfloat16(p2)),
                                 p3 - __bfloat162float(__float2bfloat16(p3)));
                aPl[2] = packbf2(p4 - __bfloat162float(__float2bfloat16(p4)),
                                 p5 - __bfloat162float(__float2bfloat16(p5)));
                aPl[3] = packbf2(p6 - __bfloat162float(__float2bfloat16(p6)),
                                 p7 - __bfloat162float(__float2bfloat16(p7)));
            }
#pragma unroll
            for (int ng = 0; ng < 8; ng++) {
                uint32_t bh[4], bl[4];
                const uint32_t va = ((ks * 16 + lr) * FLD + ng * 16 + lcg) * 2;
                ldsm4t(bh, cVH + va);
                ldsm4t(bl, cVL + va);
                mma16816(Oacc[2 * ng], aPh, bh[0], bh[1]);
                mma16816(Oacc[2 * ng], aPh, bl[0], bl[1]);
                mma16816(Oacc[2 * ng], aPl, bh[0], bh[1]);
                mma16816(Oacc[2 * ng + 1], aPh, bh[2], bh[3]);
                mma16816(Oacc[2 * ng + 1], aPh, bl[2], bl[3]);
                mma16816(Oacc[2 * ng + 1], aPl, bh[2], bh[3]);
            }
        }
        __syncthreads();
    }

    const float inv0 = 1.0f / l0, inv1 = 1.0f / l1;
    const size_t rb0 = ((size_t)(b * T_) + grow0) * ATTN_ + h * D_;
    const size_t rb1 = ((size_t)(b * T_) + grow1) * ATTN_ + h * D_;
    const int nn = (lane & 3) << 1;
#pragma unroll
    for (int nt = 0; nt < 16; nt++) {
        const int col = nt * 8 + nn;
        {
            const float v0 = Oacc[nt][0] * inv0, v1 = Oacc[nt][1] * inv0;
            const __nv_bfloat16 h0 = __float2bfloat16(v0), h1 = __float2bfloat16(v1);
            *(__nv_bfloat162*)(Yh + rb0 + col) = __halves2bfloat162(h0, h1);
            *(__nv_bfloat162*)(Yl + rb0 + col) = __halves2bfloat162(
                __float2bfloat16(v0 - __bfloat162float(h0)),
                __float2bfloat16(v1 - __bfloat162float(h1)));
        }
        {
            const float v0 = Oacc[nt][2] * inv1, v1 = Oacc[nt][3] * inv1;
            const __nv_bfloat16 h0 = __float2bfloat16(v0), h1 = __float2bfloat16(v1);
            *(__nv_bfloat162*)(Yh + rb1 + col) = __halves2bfloat162(h0, h1);
            *(__nv_bfloat162*)(Yl + rb1 + col) = __halves2bfloat162(
                __float2bfloat16(v0 - __bfloat162float(h0)),
                __float2bfloat16(v1 - __bfloat162float(h1)));
        }
    }
}

// ---------------------------------------------------------------------------
// Host side. Launch order: #3=qkv (ncu -s 5 catches? order: 0 rope, 1 split_x,
// 2 split_w, 3 qkv, 4 flash, 5 out_gemm).
// ---------------------------------------------------------------------------
extern "C" void kernel_launch(void* const* d_in, const int* in_sizes, int n_in,
                              void* d_out, int out_size)
{
    const float* x    = (const float*)d_in[0];
    const float* wq_w = (const float*)d_in[3];
    const float* wq_b = (const float*)d_in[4];
    const float* wk_w = (const float*)d_in[5];
    const float* wk_b = (const float*)d_in[6];
    const float* wv_w = (const float*)d_in[7];
    const float* wv_b = (const float*)d_in[8];
    const float* wo_w = (const float*)d_in[9];
    const float* wo_b = (const float*)d_in[10];
    float* out = (float*)d_out;

    float *cosp, *sinp;
    __nv_bfloat16 *xh, *xl, *qh, *ql, *kh, *kl, *vh, *vl, *yh, *yl, *wh, *wl;
    cudaGetSymbolAddress((void**)&cosp, g_cosT);
    cudaGetSymbolAddress((void**)&sinp, g_sinT);
    cudaGetSymbolAddress((void**)&xh, g_xh);
    cudaGetSymbolAddress((void**)&xl, g_xl);
    cudaGetSymbolAddress((void**)&qh, g_qh);
    cudaGetSymbolAddress((void**)&ql, g_ql);
    cudaGetSymbolAddress((void**)&kh, g_kh);
    cudaGetSymbolAddress((void**)&kl, g_kl);
    cudaGetSymbolAddress((void**)&vh, g_vh);
    cudaGetSymbolAddress((void**)&vl, g_vl);
    cudaGetSymbolAddress((void**)&yh, g_yh);
    cudaGetSymbolAddress((void**)&yl, g_yl);
    cudaGetSymbolAddress((void**)&wh, g_wh);
    cudaGetSymbolAddress((void**)&wl, g_wl);

    const size_t WSZ = (size_t)ATTN_ * ATTN_;

    rope_table_kernel<<<T_, 64>>>(cosp, sinp);
    const int n4x = BT_ * ATTN_ / 4;
    split_kernel<<<n4x / 256, 256>>>((const float4*)x, (__nv_bfloat162*)xh,
                                     (__nv_bfloat162*)xl, n4x);
    const int n4w = ATTN_ * ATTN_ / 4;
    split_w_kernel<<<dim3(n4w / 256, 1, 4), 256>>>(wq_w, wk_w, wv_w, wo_w,
                                                   (__nv_bfloat162*)wh,
                                                   (__nv_bfloat162*)wl, n4w);

    cudaFuncSetAttribute(qkv_gemm, cudaFuncAttributeMaxDynamicSharedMemorySize, GEMM_SMEM);
    cudaFuncSetAttribute(out_gemm, cudaFuncAttributeMaxDynamicSharedMemorySize, GEMM_SMEM);
    cudaFuncSetAttribute(flash_mma, cudaFuncAttributeMaxDynamicSharedMemorySize, FSMEM);

    qkv_gemm<<<dim3(24, BT_ / GBM), GTHREADS, GEMM_SMEM>>>(xh, xl, wh, wl,
                                                           wq_b, wk_b, wv_b,
                                                           qh, ql, kh, kl, vh, vl,
                                                           cosp, sinp);
    flash_mma<<<dim3(T_ / 128, H_, B_), 256, FSMEM>>>(qh, ql, kh, kl, vh, vl, yh, yl);

    out_gemm<<<dim3(ATTN_ / GBN, BT_ / GBM), GTHREADS, GEMM_SMEM>>>(yh, yl,
                                                                    wh + 3 * WSZ, wl + 3 * WSZ,
                                                                    wo_b, out);
}

// round 8
// speedup vs baseline: 1.0191x; 1.0191x over previous
#include <cuda_runtime.h>
#include <cuda_bf16.h>
#include <math.h>
#include <stdint.h>

#define B_    4
#define T_    2048
#define H_    16
#define D_    128
#define ATTN_ 2048
#define BT_   (B_*T_)

// ---------------------------------------------------------------------------
// Scratch (__device__ globals). Weights concat: slots 0-2 = wq,wk,wv; 3 = wo.
// ---------------------------------------------------------------------------
__device__ __nv_bfloat16 g_xh[(size_t)BT_ * ATTN_];
__device__ __nv_bfloat16 g_xl[(size_t)BT_ * ATTN_];
__device__ __nv_bfloat16 g_qh[(size_t)BT_ * ATTN_];
__device__ __nv_bfloat16 g_ql[(size_t)BT_ * ATTN_];
__device__ __nv_bfloat16 g_kh[(size_t)BT_ * ATTN_];
__device__ __nv_bfloat16 g_kl[(size_t)BT_ * ATTN_];
__device__ __nv_bfloat16 g_vh[(size_t)BT_ * ATTN_];
__device__ __nv_bfloat16 g_vl[(size_t)BT_ * ATTN_];
__device__ __nv_bfloat16 g_yh[(size_t)BT_ * ATTN_];
__device__ __nv_bfloat16 g_yl[(size_t)BT_ * ATTN_];
__device__ __nv_bfloat16 g_wh[(size_t)4 * ATTN_ * ATTN_];
__device__ __nv_bfloat16 g_wl[(size_t)4 * ATTN_ * ATTN_];
__device__ float g_cosT[T_ * 64];
__device__ float g_sinT[T_ * 64];

// ---------------------------------------------------------------------------
// PTX helpers
// ---------------------------------------------------------------------------
__device__ __forceinline__ uint32_t smem_u32(const void* p) {
    uint32_t a;
    asm("{ .reg .u64 t; cvta.to.shared.u64 t, %1; cvt.u32.u64 %0, t; }" : "=r"(a) : "l"(p));
    return a;
}

#define CP_ASYNC16(dst, src) \
    asm volatile("cp.async.cg.shared.global [%0], [%1], 16;" :: "r"(dst), "l"(src))
#define CP_COMMIT() asm volatile("cp.async.commit_group;" ::: "memory")
#define CP_WAIT(n)  asm volatile("cp.async.wait_group %0;" :: "n"(n) : "memory")

__device__ __forceinline__ void ldsm4(uint32_t* r, uint32_t addr) {
    asm volatile("ldmatrix.sync.aligned.m8n8.x4.shared.b16 {%0,%1,%2,%3}, [%4];"
                 : "=r"(r[0]), "=r"(r[1]), "=r"(r[2]), "=r"(r[3]) : "r"(addr));
}
__device__ __forceinline__ void ldsm4t(uint32_t* r, uint32_t addr) {
    asm volatile("ldmatrix.sync.aligned.m8n8.x4.trans.shared.b16 {%0,%1,%2,%3}, [%4];"
                 : "=r"(r[0]), "=r"(r[1]), "=r"(r[2]), "=r"(r[3]) : "r"(addr));
}

__device__ __forceinline__ void mma16816(float* c, const uint32_t* a,
                                         uint32_t b0, uint32_t b1) {
    asm volatile(
        "mma.sync.aligned.m16n8k16.row.col.f32.bf16.bf16.f32 "
        "{%0,%1,%2,%3}, {%4,%5,%6,%7}, {%8,%9}, {%0,%1,%2,%3};"
        : "+f"(c[0]), "+f"(c[1]), "+f"(c[2]), "+f"(c[3])
        : "r"(a[0]), "r"(a[1]), "r"(a[2]), "r"(a[3]), "r"(b0), "r"(b1));
}

__device__ __forceinline__ uint32_t packbf2(float a, float b) {
    __nv_bfloat162 t = __halves2bfloat162(__float2bfloat16(a), __float2bfloat16(b));
    return *(uint32_t*)&t;
}

// ---------------------------------------------------------------------------
// Elementwise kernels
// ---------------------------------------------------------------------------
__global__ void rope_table_kernel(float* __restrict__ cosT, float* __restrict__ sinT) {
    const int t = blockIdx.x;
    const int i = threadIdx.x;
    const float kFreq = 0.07195578415606394f;  // ln(10000)/128
    const float inv = expf((float)(2 * i) * -kFreq);
    const float ang = (float)t * inv;
    float s, c;
    sincosf(ang, &s, &c);
    cosT[t * 64 + i] = c;
    sinT[t * 64 + i] = s;
}

__global__ void split_kernel(const float4* __restrict__ src,
                             __nv_bfloat162* __restrict__ hi,
                             __nv_bfloat162* __restrict__ lo, int n4) {
    int i = blockIdx.x * blockDim.x + threadIdx.x;
    if (i >= n4) return;
    float4 v = src[i];
    __nv_bfloat16 h0 = __float2bfloat16(v.x);
    __nv_bfloat16 h1 = __float2bfloat16(v.y);
    __nv_bfloat16 h2 = __float2bfloat16(v.z);
    __nv_bfloat16 h3 = __float2bfloat16(v.w);
    hi[2 * i]     = __halves2bfloat162(h0, h1);
    hi[2 * i + 1] = __halves2bfloat162(h2, h3);
    lo[2 * i]     = __halves2bfloat162(__float2bfloat16(v.x - __bfloat162float(h0)),
                                       __float2bfloat16(v.y - __bfloat162float(h1)));
    lo[2 * i + 1] = __halves2bfloat162(__float2bfloat16(v.z - __bfloat162float(h2)),
                                       __float2bfloat16(v.w - __bfloat162float(h3)));
}

__global__ void split_w_kernel(const float* __restrict__ w0, const float* __restrict__ w1,
                               const float* __restrict__ w2, const float* __restrict__ w3,
                               __nv_bfloat162* __restrict__ hi, __nv_bfloat162* __restrict__ lo,
                               int n4) {
    int i = blockIdx.x * blockDim.x + threadIdx.x;
    if (i >= n4) return;
    const int z = blockIdx.z;
    const float* src = (z == 0) ? w0 : (z == 1) ? w1 : (z == 2) ? w2 : w3;
    float4 v = ((const float4*)src)[i];
    const size_t off = (size_t)z * n4 * 2;
    __nv_bfloat16 h0 = __float2bfloat16(v.x);
    __nv_bfloat16 h1 = __float2bfloat16(v.y);
    __nv_bfloat16 h2 = __float2bfloat16(v.z);
    __nv_bfloat16 h3 = __float2bfloat16(v.w);
    hi[off + 2 * i]     = __halves2bfloat162(h0, h1);
    hi[off + 2 * i + 1] = __halves2bfloat162(h2, h3);
    lo[off + 2 * i]     = __halves2bfloat162(__float2bfloat16(v.x - __bfloat162float(h0)),
                                             __float2bfloat16(v.y - __bfloat162float(h1)));
    lo[off + 2 * i + 1] = __halves2bfloat162(__float2bfloat16(v.z - __bfloat162float(h2)),
                                             __float2bfloat16(v.w - __bfloat162float(h3)));
}

// ---------------------------------------------------------------------------
// GEMM v4: CTA 128x128, 256 threads = 8 warps (2 M x 4 N), warp tile 64x32.
// BK=32, 2-stage, smem 80KB/CTA -> TWO CTAs resident per SM (barrier overlap).
// ---------------------------------------------------------------------------
static constexpr int GBM = 128, GBN = 128, GBK = 32;
static constexpr int LDSE = 40;                 // padded row pitch (elems)
static constexpr int ARRB = 128 * LDSE * 2;     // 10240 B per array
static constexpr int STB  = 4 * ARRB;           // 40960 B per stage
static constexpr int GSMEM = 2 * STB;           // 81920 B
static constexpr int GTH = 256;

struct GemmCore {
    __device__ static __forceinline__ void run(
        uint32_t sBase, float (&acc)[4][4][4],
        const __nv_bfloat16* gAh, const __nv_bfloat16* gAl,
        const __nv_bfloat16* gWh, const __nv_bfloat16* gWl,
        int tid, int wm, int wn, int lr, int lc)
    {
        const int cc = tid & 3;        // 16B chunk within 64B row (BK=32 bf16)
        const int rb = tid >> 2;       // 0..63
        const int NIT = ATTN_ / GBK;   // 64

        auto load_stage = [&](uint32_t st, int k0) {
#pragma unroll
            for (int bb = 0; bb < 2; bb++) {
                const int r = bb * 64 + rb;
                const uint32_t so = r * (LDSE * 2) + cc * 16;
                const size_t go = (size_t)r * ATTN_ + k0 + cc * 8;
                CP_ASYNC16(st + so,            gAh + go);
                CP_ASYNC16(st + ARRB + so,     gAl + go);
                CP_ASYNC16(st + 2 * ARRB + so, gWh + go);
                CP_ASYNC16(st + 3 * ARRB + so, gWl + go);
            }
            CP_COMMIT();
        };

        load_stage(sBase, 0);

        for (int kt = 0; kt < NIT; kt++) {
            if (kt + 1 < NIT) {
                load_stage(sBase + ((kt + 1) & 1) * STB, (kt + 1) * GBK);
                CP_WAIT(1);
            } else {
                CP_WAIT(0);
            }
            __syncthreads();

            const uint32_t st  = sBase + (kt & 1) * STB;
            const uint32_t sAh = st;
            const uint32_t sAl = st + ARRB;
            const uint32_t sWh = st + 2 * ARRB;
            const uint32_t sWl = st + 3 * ARRB;

#pragma unroll
            for (int ks = 0; ks < 2; ks++) {
                const int kc = ks * 16 + lc;
                uint32_t ah[4][4], whf[2][4], wlf[2][4];
#pragma unroll
                for (int mt = 0; mt < 4; mt++)
                    ldsm4(ah[mt], sAh + ((wm + mt * 16 + lr) * LDSE + kc) * 2);
#pragma unroll
                for (int g = 0; g < 2; g++)
                    ldsm4(whf[g], sWh + ((wn + g * 16 + lr) * LDSE + kc) * 2);
#pragma unroll
                for (int g = 0; g < 2; g++)
                    ldsm4(wlf[g], sWl + ((wn + g * 16 + lr) * LDSE + kc) * 2);

                // Ah * Wh
#pragma unroll
                for (int mt = 0; mt < 4; mt++)
#pragma unroll
                    for (int nt = 0; nt < 4; nt++)
                        mma16816(acc[mt][nt], ah[mt], whf[nt >> 1][nt & 1], whf[nt >> 1][(nt & 1) + 2]);
                // Ah * Wl
#pragma unroll
                for (int mt = 0; mt < 4; mt++)
#pragma unroll
                    for (int nt = 0; nt < 4; nt++)
                        mma16816(acc[mt][nt], ah[mt], wlf[nt >> 1][nt & 1], wlf[nt >> 1][(nt & 1) + 2]);
                // Al * Wh (reload A frags)
#pragma unroll
                for (int mt = 0; mt < 4; mt++)
                    ldsm4(ah[mt], sAl + ((wm + mt * 16 + lr) * LDSE + kc) * 2);
#pragma unroll
                for (int mt = 0; mt < 4; mt++)
#pragma unroll
                    for (int nt = 0; nt < 4; nt++)
                        mma16816(acc[mt][nt], ah[mt], whf[nt >> 1][nt & 1], whf[nt >> 1][(nt & 1) + 2]);
            }
            __syncthreads();
        }
    }
};

// ---------------------------------------------------------------------------
// Fused QKV projection GEMM. grid (48, 64). blockIdx.x>>4 : 0=Q,1=K,2=V.
// ---------------------------------------------------------------------------
__global__ void __launch_bounds__(GTH, 2) qkv_gemm(
    const __nv_bfloat16* __restrict__ Xh, const __nv_bfloat16* __restrict__ Xl,
    const __nv_bfloat16* __restrict__ Wh, const __nv_bfloat16* __restrict__ Wl,
    const float* __restrict__ bq, const float* __restrict__ bk, const float* __restrict__ bv,
    __nv_bfloat16* __restrict__ QH, __nv_bfloat16* __restrict__ QL,
    __nv_bfloat16* __restrict__ KH, __nv_bfloat16* __restrict__ KL,
    __nv_bfloat16* __restrict__ VH, __nv_bfloat16* __restrict__ VL,
    const float* __restrict__ cosT, const float* __restrict__ sinT)
{
    extern __shared__ char dsm[];
    const uint32_t sBase = smem_u32(dsm);

    const int tid  = threadIdx.x;
    const int wid  = tid >> 5;
    const int lane = tid & 31;
    const int wm   = (wid >> 2) * 64;
    const int wn   = (wid & 3) * 32;
    const int bm   = blockIdx.y * GBM;
    const int qkv  = blockIdx.x >> 4;
    const int bnl  = (blockIdx.x & 15) * GBN;
    const int bng  = blockIdx.x * GBN;

    float acc[4][4][4];
#pragma unroll
    for (int mt = 0; mt < 4; mt++)
#pragma unroll
        for (int nt = 0; nt < 4; nt++)
#pragma unroll
            for (int e = 0; e < 4; e++) acc[mt][nt][e] = 0.f;

    GemmCore::run(sBase, acc,
                  Xh + (size_t)bm * ATTN_, Xl + (size_t)bm * ATTN_,
                  Wh + (size_t)bng * ATTN_, Wl + (size_t)bng * ATTN_,
                  tid, wm, wn, lane & 15, (lane >> 4) << 3);

    const float* bias = (qkv == 0) ? bq : (qkv == 1) ? bk : bv;
    __nv_bfloat16* CH = (qkv == 0) ? QH : (qkv == 1) ? KH : VH;
    __nv_bfloat16* CL = (qkv == 0) ? QL : (qkv == 1) ? KL : VL;
    const bool rope  = (qkv != 2);
    const bool scale = (qkv == 0);
    const float qscale = 0.08838834764831843f;

    const int rr = lane >> 2;
    const int nn = (lane & 3) * 2;
#pragma unroll
    for (int mt = 0; mt < 4; mt++) {
#pragma unroll
        for (int half = 0; half < 2; half++) {
            const int m = bm + wm + mt * 16 + rr + half * 8;
            const int pos = m & (T_ - 1);
#pragma unroll
            for (int nt = 0; nt < 4; nt++) {
                const int n0 = bnl + wn + nt * 8 + nn;
                float v0 = acc[mt][nt][half * 2 + 0] + __ldg(&bias[n0]);
                float v1 = acc[mt][nt][half * 2 + 1] + __ldg(&bias[n0 + 1]);
                if (rope) {
                    const int pi = (n0 & (D_ - 1)) >> 1;
                    const float cv = __ldg(&cosT[pos * 64 + pi]);
                    const float sv = __ldg(&sinT[pos * 64 + pi]);
                    const float t1 = v0, t2 = v1;
                    v0 = t1 * cv - t2 * sv;
                    v1 = t1 * sv + t2 * cv;
                }
                if (scale) { v0 *= qscale; v1 *= qscale; }
                const __nv_bfloat16 h0 = __float2bfloat16(v0);
                const __nv_bfloat16 h1 = __float2bfloat16(v1);
                *(__nv_bfloat162*)(CH + (size_t)m * ATTN_ + n0) = __halves2bfloat162(h0, h1);
                *(__nv_bfloat162*)(CL + (size_t)m * ATTN_ + n0) = __halves2bfloat162(
                    __float2bfloat16(v0 - __bfloat162float(h0)),
                    __float2bfloat16(v1 - __bfloat162float(h1)));
            }
        }
    }
}

// ---------------------------------------------------------------------------
// Output projection GEMM: fp32 out + bias. grid (16, 64).
// ---------------------------------------------------------------------------
__global__ void __launch_bounds__(GTH, 2) out_gemm(
    const __nv_bfloat16* __restrict__ Ah, const __nv_bfloat16* __restrict__ Al,
    const __nv_bfloat16* __restrict__ Wh, const __nv_bfloat16* __restrict__ Wl,
    const float* __restrict__ bias, float* __restrict__ Cf)
{
    extern __shared__ char dsm[];
    const uint32_t sBase = smem_u32(dsm);

    const int tid  = threadIdx.x;
    const int wid  = tid >> 5;
    const int lane = tid & 31;
    const int wm   = (wid >> 2) * 64;
    const int wn   = (wid & 3) * 32;
    const int bm   = blockIdx.y * GBM;
    const int bn   = blockIdx.x * GBN;

    float acc[4][4][4];
#pragma unroll
    for (int mt = 0; mt < 4; mt++)
#pragma unroll
        for (int nt = 0; nt < 4; nt++)
#pragma unroll
            for (int e = 0; e < 4; e++) acc[mt][nt][e] = 0.f;

    GemmCore::run(sBase, acc,
                  Ah + (size_t)bm * ATTN_, Al + (size_t)bm * ATTN_,
                  Wh + (size_t)bn * ATTN_, Wl + (size_t)bn * ATTN_,
                  tid, wm, wn, lane & 15, (lane >> 4) << 3);

    const int rr = lane >> 2;
    const int nn = (lane & 3) * 2;
#pragma unroll
    for (int mt = 0; mt < 4; mt++) {
#pragma unroll
        for (int half = 0; half < 2; half++) {
            const int m = bm + wm + mt * 16 + rr + half * 8;
#pragma unroll
            for (int nt = 0; nt < 4; nt++) {
                const int n0 = bn + wn + nt * 8 + nn;
                const float v0 = acc[mt][nt][half * 2 + 0] + __ldg(&bias[n0]);
                const float v1 = acc[mt][nt][half * 2 + 1] + __ldg(&bias[n0 + 1]);
                *(float2*)(Cf + (size_t)m * ATTN_ + n0) = make_float2(v0, v1);
            }
        }
    }
}

// ---------------------------------------------------------------------------
// Tensor-core causal flash attention (unchanged, passing).
// ---------------------------------------------------------------------------
static constexpr int FLD = 136;
static constexpr int FQB = 128 * FLD * 2;
static constexpr int FKB = 64 * FLD * 2;
static constexpr int FSTG = 4 * FKB;
static constexpr int FSMEM = 2 * FQB + 2 * FSTG;

__global__ void __launch_bounds__(256, 1) flash_mma(
    const __nv_bfloat16* __restrict__ Qh, const __nv_bfloat16* __restrict__ Ql,
    const __nv_bfloat16* __restrict__ Kh, const __nv_bfloat16* __restrict__ Kl,
    const __nv_bfloat16* __restrict__ Vh, const __nv_bfloat16* __restrict__ Vl,
    __nv_bfloat16* __restrict__ Yh, __nv_bfloat16* __restrict__ Yl)
{
    extern __shared__ char fsm[];
    const uint32_t sb  = smem_u32(fsm);
    const uint32_t sQH = sb;
    const uint32_t sQL = sb + FQB;
    const uint32_t sKV = sb + 2 * FQB;

    const int qt = blockIdx.x, h = blockIdx.y, b = blockIdx.z;
    const int tid = threadIdx.x, wid = tid >> 5, lane = tid & 31;
    const int wm = wid * 16;
    const int lr = lane & 15;
    const int lcg = (lane >> 4) << 3;

    const int ccf = tid & 15;
    const int r0f = tid >> 4;

    {
        const __nv_bfloat16* qh_g = Qh + ((size_t)(b * T_ + qt * 128)) * ATTN_ + h * D_;
        const __nv_bfloat16* ql_g = Ql + ((size_t)(b * T_ + qt * 128)) * ATTN_ + h * D_;
#pragma unroll
        for (int bb = 0; bb < 8; bb++) {
            const int r = bb * 16 + r0f;
            const uint32_t so = r * (FLD * 2) + ccf * 16;
            const size_t go = (size_t)r * ATTN_ + ccf * 8;
            CP_ASYNC16(sQH + so, qh_g + go);
            CP_ASYNC16(sQL + so, ql_g + go);
        }
        CP_COMMIT();
    }

    const int nkv = 2 * qt + 2;

    auto issue_kv = [&](int j) {
        const uint32_t st = sKV + (j & 1) * FSTG;
        const size_t base = ((size_t)(b * T_ + j * 64)) * ATTN_ + h * D_;
#pragma unroll
        for (int bb = 0; bb < 4; bb++) {
            const int r = bb * 16 + r0f;
            const uint32_t so = r * (FLD * 2) + ccf * 16;
            const size_t go = base + (size_t)r * ATTN_ + ccf * 8;
            CP_ASYNC16(st + so, Kh + go);
            CP_ASYNC16(st + FKB + so, Kl + go);
            CP_ASYNC16(st + 2 * FKB + so, Vh + go);
            CP_ASYNC16(st + 3 * FKB + so, Vl + go);
        }
        CP_COMMIT();
    };

    issue_kv(0);

    float Oacc[16][4];
#pragma unroll
    for (int nt = 0; nt < 16; nt++)
#pragma unroll
        for (int e = 0; e < 4; e++) Oacc[nt][e] = 0.f;
    float m0 = -1e30f, m1 = -1e30f, l0 = 0.f, l1 = 0.f;

    const int grow0 = qt * 128 + wm + (lane >> 2);
    const int grow1 = grow0 + 8;

    for (int j = 0; j < nkv; j++) {
        if (j + 1 < nkv) {
            issue_kv(j + 1);
            CP_WAIT(1);
        } else {
            CP_WAIT(0);
        }
        __syncthreads();

        const uint32_t st  = sKV + (j & 1) * FSTG;
        const uint32_t cKH = st;
        const uint32_t cKL = st + FKB;
        const uint32_t cVH = st + 2 * FKB;
        const uint32_t cVL = st + 3 * FKB;

        float sc[8][4];
#pragma unroll
        for (int nt = 0; nt < 8; nt++)
#pragma unroll
            for (int e = 0; e < 4; e++) sc[nt][e] = 0.f;

#pragma unroll 2
        for (int ks = 0; ks < 8; ks++) {
            const int kc = ks * 16 + lcg;
            uint32_t aQh[4], aQl[4], kh[4][4], kl[4][4];
            ldsm4(aQh, sQH + ((wm + lr) * FLD + kc) * 2);
            ldsm4(aQl, sQL + ((wm + lr) * FLD + kc) * 2);
#pragma unroll
            for (int g = 0; g < 4; g++) {
                ldsm4(kh[g], cKH + ((g * 16 + lr) * FLD + kc) * 2);
                ldsm4(kl[g], cKL + ((g * 16 + lr) * FLD + kc) * 2);
            }
#pragma unroll
            for (int nt = 0; nt < 8; nt++) {
                const uint32_t b0h = kh[nt >> 1][nt & 1], b1h = kh[nt >> 1][(nt & 1) + 2];
                mma16816(sc[nt], aQh, b0h, b1h);
                mma16816(sc[nt], aQh, kl[nt >> 1][nt & 1], kl[nt >> 1][(nt & 1) + 2]);
                mma16816(sc[nt], aQl, b0h, b1h);
            }
        }

        if (j >= 2 * qt) {
            const int c0 = j * 64 + ((lane & 3) << 1);
#pragma unroll
            for (int nt = 0; nt < 8; nt++) {
                const int gc = c0 + nt * 8;
                if (gc > grow0)     sc[nt][0] = -1e30f;
                if (gc + 1 > grow0) sc[nt][1] = -1e30f;
                if (gc > grow1)     sc[nt][2] = -1e30f;
                if (gc + 1 > grow1) sc[nt][3] = -1e30f;
            }
        }
        float mx0 = -1e30f, mx1 = -1e30f;
#pragma unroll
        for (int nt = 0; nt < 8; nt++) {
            mx0 = fmaxf(mx0, fmaxf(sc[nt][0], sc[nt][1]));
            mx1 = fmaxf(mx1, fmaxf(sc[nt][2], sc[nt][3]));
        }
        mx0 = fmaxf(mx0, __shfl_xor_sync(0xffffffffu, mx0, 1));
        mx0 = fmaxf(mx0, __shfl_xor_sync(0xffffffffu, mx0, 2));
        mx1 = fmaxf(mx1, __shfl_xor_sync(0xffffffffu, mx1, 1));
        mx1 = fmaxf(mx1, __shfl_xor_sync(0xffffffffu, mx1, 2));
        const float mn0 = fmaxf(m0, mx0), mn1 = fmaxf(m1, mx1);
        const float al0 = __expf(m0 - mn0), al1 = __expf(m1 - mn1);
        float ls0 = 0.f, ls1 = 0.f;
#pragma unroll
        for (int nt = 0; nt < 8; nt++) {
            sc[nt][0] = __expf(sc[nt][0] - mn0);
            sc[nt][1] = __expf(sc[nt][1] - mn0);
            sc[nt][2] = __expf(sc[nt][2] - mn1);
            sc[nt][3] = __expf(sc[nt][3] - mn1);
            ls0 += sc[nt][0] + sc[nt][1];
            ls1 += sc[nt][2] + sc[nt][3];
        }
        ls0 += __shfl_xor_sync(0xffffffffu, ls0, 1);
        ls0 += __shfl_xor_sync(0xffffffffu, ls0, 2);
        ls1 += __shfl_xor_sync(0xffffffffu, ls1, 1);
        ls1 += __shfl_xor_sync(0xffffffffu, ls1, 2);
        l0 = l0 * al0 + ls0; m0 = mn0;
        l1 = l1 * al1 + ls1; m1 = mn1;
#pragma unroll
        for (int nt = 0; nt < 16; nt++) {
            Oacc[nt][0] *= al0; Oacc[nt][1] *= al0;
            Oacc[nt][2] *= al1; Oacc[nt][3] *= al1;
        }

#pragma unroll
        for (int ks = 0; ks < 4; ks++) {
            uint32_t aPh[4], aPl[4];
            {
                const float p0 = sc[2 * ks][0],     p1 = sc[2 * ks][1];
                const float p2 = sc[2 * ks][2],     p3 = sc[2 * ks][3];
                const float p4 = sc[2 * ks + 1][0], p5 = sc[2 * ks + 1][1];
                const float p6 = sc[2 * ks + 1][2], p7 = sc[2 * ks + 1][3];
                aPh[0] = packbf2(p0, p1);
                aPh[1] = packbf2(p2, p3);
                aPh[2] = packbf2(p4, p5);
                aPh[3] = packbf2(p6, p7);
                aPl[0] = packbf2(p0 - __bfloat162float(__float2bfloat16(p0)),
                                 p1 - __bfloat162float(__float2bfloat16(p1)));
                aPl[1] = packbf2(p2 - __bfloat162float(__float2bfloat16(p2)),
                                 p3 - __bfloat162float(__float2bfloat16(p3)));
                aPl[2] = packbf2(p4 - __bfloat162float(__float2bfloat16(p4)),
                                 p5 - __bfloat162float(__float2bfloat16(p5)));
                aPl[3] = packbf2(p6 - __bfloat162float(__float2bfloat16(p6)),
                                 p7 - __bfloat162float(__float2bfloat16(p7)));
            }
#pragma unroll
            for (int ng = 0; ng < 8; ng++) {
                uint32_t bh[4], bl[4];
                const uint32_t va = ((ks * 16 + lr) * FLD + ng * 16 + lcg) * 2;
                ldsm4t(bh, cVH + va);
                ldsm4t(bl, cVL + va);
                mma16816(Oacc[2 * ng], aPh, bh[0], bh[1]);
                mma16816(Oacc[2 * ng], aPh, bl[0], bl[1]);
                mma16816(Oacc[2 * ng], aPl, bh[0], bh[1]);
                mma16816(Oacc[2 * ng + 1], aPh, bh[2], bh[3]);
                mma16816(Oacc[2 * ng + 1], aPh, bl[2], bl[3]);
                mma16816(Oacc[2 * ng + 1], aPl, bh[2], bh[3]);
            }
        }
        __syncthreads();
    }

    const float inv0 = 1.0f / l0, inv1 = 1.0f / l1;
    const size_t rb0 = ((size_t)(b * T_) + grow0) * ATTN_ + h * D_;
    const size_t rb1 = ((size_t)(b * T_) + grow1) * ATTN_ + h * D_;
    const int nn = (lane & 3) << 1;
#pragma unroll
    for (int nt = 0; nt < 16; nt++) {
        const int col = nt * 8 + nn;
        {
            const float v0 = Oacc[nt][0] * inv0, v1 = Oacc[nt][1] * inv0;
            const __nv_bfloat16 h0 = __float2bfloat16(v0), h1 = __float2bfloat16(v1);
            *(__nv_bfloat162*)(Yh + rb0 + col) = __halves2bfloat162(h0, h1);
            *(__nv_bfloat162*)(Yl + rb0 + col) = __halves2bfloat162(
                __float2bfloat16(v0 - __bfloat162float(h0)),
                __float2bfloat16(v1 - __bfloat162float(h1)));
        }
        {
            const float v0 = Oacc[nt][2] * inv1, v1 = Oacc[nt][3] * inv1;
            const __nv_bfloat16 h0 = __float2bfloat16(v0), h1 = __float2bfloat16(v1);
            *(__nv_bfloat162*)(Yh + rb1 + col) = __halves2bfloat162(h0, h1);
            *(__nv_bfloat162*)(Yl + rb1 + col) = __halves2bfloat162(
                __float2bfloat16(v0 - __bfloat162float(h0)),
                __float2bfloat16(v1 - __bfloat162float(h1)));
        }
    }
}

// ---------------------------------------------------------------------------
// Host side. Launch order: 0 rope, 1 split_x, 2 split_w, 3 qkv, 4 flash, 5 out.
// ---------------------------------------------------------------------------
extern "C" void kernel_launch(void* const* d_in, const int* in_sizes, int n_in,
                              void* d_out, int out_size)
{
    const float* x    = (const float*)d_in[0];
    const float* wq_w = (const float*)d_in[3];
    const float* wq_b = (const float*)d_in[4];
    const float* wk_w = (const float*)d_in[5];
    const float* wk_b = (const float*)d_in[6];
    const float* wv_w = (const float*)d_in[7];
    const float* wv_b = (const float*)d_in[8];
    const float* wo_w = (const float*)d_in[9];
    const float* wo_b = (const float*)d_in[10];
    float* out = (float*)d_out;

    float *cosp, *sinp;
    __nv_bfloat16 *xh, *xl, *qh, *ql, *kh, *kl, *vh, *vl, *yh, *yl, *wh, *wl;
    cudaGetSymbolAddress((void**)&cosp, g_cosT);
    cudaGetSymbolAddress((void**)&sinp, g_sinT);
    cudaGetSymbolAddress((void**)&xh, g_xh);
    cudaGetSymbolAddress((void**)&xl, g_xl);
    cudaGetSymbolAddress((void**)&qh, g_qh);
    cudaGetSymbolAddress((void**)&ql, g_ql);
    cudaGetSymbolAddress((void**)&kh, g_kh);
    cudaGetSymbolAddress((void**)&kl, g_kl);
    cudaGetSymbolAddress((void**)&vh, g_vh);
    cudaGetSymbolAddress((void**)&vl, g_vl);
    cudaGetSymbolAddress((void**)&yh, g_yh);
    cudaGetSymbolAddress((void**)&yl, g_yl);
    cudaGetSymbolAddress((void**)&wh, g_wh);
    cudaGetSymbolAddress((void**)&wl, g_wl);

    const size_t WSZ = (size_t)ATTN_ * ATTN_;

    rope_table_kernel<<<T_, 64>>>(cosp, sinp);
    const int n4x = BT_ * ATTN_ / 4;
    split_kernel<<<n4x / 256, 256>>>((const float4*)x, (__nv_bfloat162*)xh,
                                     (__nv_bfloat162*)xl, n4x);
    const int n4w = ATTN_ * ATTN_ / 4;
    split_w_kernel<<<dim3(n4w / 256, 1, 4), 256>>>(wq_w, wk_w, wv_w, wo_w,
                                                   (__nv_bfloat162*)wh,
                                                   (__nv_bfloat162*)wl, n4w);

    cudaFuncSetAttribute(qkv_gemm, cudaFuncAttributeMaxDynamicSharedMemorySize, GSMEM);
    cudaFuncSetAttribute(out_gemm, cudaFuncAttributeMaxDynamicSharedMemorySize, GSMEM);
    cudaFuncSetAttribute(flash_mma, cudaFuncAttributeMaxDynamicSharedMemorySize, FSMEM);

    qkv_gemm<<<dim3(48, BT_ / GBM), GTH, GSMEM>>>(xh, xl, wh, wl,
                                                  wq_b, wk_b, wv_b,
                                                  qh, ql, kh, kl, vh, vl,
                                                  cosp, sinp);
    flash_mma<<<dim3(T_ / 128, H_, B_), 256, FSMEM>>>(qh, ql, kh, kl, vh, vl, yh, yl);

    out_gemm<<<dim3(ATTN_ / GBN, BT_ / GBM), GTH, GSMEM>>>(yh, yl,
                                                           wh + 3 * WSZ, wl + 3 * WSZ,
                                                           wo_b, out);
}

// round 9
// speedup vs baseline: 1.0194x; 1.0003x over previous
#include <cuda_runtime.h>
#include <cuda_bf16.h>
#include <math.h>
#include <stdint.h>

#define B_    4
#define T_    2048
#define H_    16
#define D_    128
#define ATTN_ 2048
#define BT_   (B_*T_)

// ---------------------------------------------------------------------------
// Scratch (__device__ globals). Weights concat: slots 0-2 = wq,wk,wv; 3 = wo.
// ---------------------------------------------------------------------------
__device__ __nv_bfloat16 g_xh[(size_t)BT_ * ATTN_];
__device__ __nv_bfloat16 g_xl[(size_t)BT_ * ATTN_];
__device__ __nv_bfloat16 g_qh[(size_t)BT_ * ATTN_];
__device__ __nv_bfloat16 g_ql[(size_t)BT_ * ATTN_];
__device__ __nv_bfloat16 g_kh[(size_t)BT_ * ATTN_];
__device__ __nv_bfloat16 g_kl[(size_t)BT_ * ATTN_];
__device__ __nv_bfloat16 g_vh[(size_t)BT_ * ATTN_];
__device__ __nv_bfloat16 g_vl[(size_t)BT_ * ATTN_];
__device__ __nv_bfloat16 g_yh[(size_t)BT_ * ATTN_];
__device__ __nv_bfloat16 g_yl[(size_t)BT_ * ATTN_];
__device__ __nv_bfloat16 g_wh[(size_t)4 * ATTN_ * ATTN_];
__device__ __nv_bfloat16 g_wl[(size_t)4 * ATTN_ * ATTN_];
__device__ float g_cosT[T_ * 64];
__device__ float g_sinT[T_ * 64];

// ---------------------------------------------------------------------------
// PTX helpers
// ---------------------------------------------------------------------------
__device__ __forceinline__ uint32_t smem_u32(const void* p) {
    uint32_t a;
    asm("{ .reg .u64 t; cvta.to.shared.u64 t, %1; cvt.u32.u64 %0, t; }" : "=r"(a) : "l"(p));
    return a;
}

#define CP_ASYNC16(dst, src) \
    asm volatile("cp.async.cg.shared.global [%0], [%1], 16;" :: "r"(dst), "l"(src))
#define CP_COMMIT() asm volatile("cp.async.commit_group;" ::: "memory")
#define CP_WAIT(n)  asm volatile("cp.async.wait_group %0;" :: "n"(n) : "memory")

__device__ __forceinline__ void ldsm4(uint32_t* r, uint32_t addr) {
    asm volatile("ldmatrix.sync.aligned.m8n8.x4.shared.b16 {%0,%1,%2,%3}, [%4];"
                 : "=r"(r[0]), "=r"(r[1]), "=r"(r[2]), "=r"(r[3]) : "r"(addr));
}
__device__ __forceinline__ void ldsm4t(uint32_t* r, uint32_t addr) {
    asm volatile("ldmatrix.sync.aligned.m8n8.x4.trans.shared.b16 {%0,%1,%2,%3}, [%4];"
                 : "=r"(r[0]), "=r"(r[1]), "=r"(r[2]), "=r"(r[3]) : "r"(addr));
}

__device__ __forceinline__ void mma16816(float* c, const uint32_t* a,
                                         uint32_t b0, uint32_t b1) {
    asm volatile(
        "mma.sync.aligned.m16n8k16.row.col.f32.bf16.bf16.f32 "
        "{%0,%1,%2,%3}, {%4,%5,%6,%7}, {%8,%9}, {%0,%1,%2,%3};"
        : "+f"(c[0]), "+f"(c[1]), "+f"(c[2]), "+f"(c[3])
        : "r"(a[0]), "r"(a[1]), "r"(a[2]), "r"(a[3]), "r"(b0), "r"(b1));
}

__device__ __forceinline__ uint32_t packbf2(float a, float b) {
    __nv_bfloat162 t = __halves2bfloat162(__float2bfloat16(a), __float2bfloat16(b));
    return *(uint32_t*)&t;
}

// ---------------------------------------------------------------------------
// Elementwise kernels
// ---------------------------------------------------------------------------
__global__ void rope_table_kernel(float* __restrict__ cosT, float* __restrict__ sinT) {
    const int t = blockIdx.x;
    const int i = threadIdx.x;
    const float kFreq = 0.07195578415606394f;  // ln(10000)/128
    const float inv = expf((float)(2 * i) * -kFreq);
    const float ang = (float)t * inv;
    float s, c;
    sincosf(ang, &s, &c);
    cosT[t * 64 + i] = c;
    sinT[t * 64 + i] = s;
}

__global__ void split_kernel(const float4* __restrict__ src,
                             __nv_bfloat162* __restrict__ hi,
                             __nv_bfloat162* __restrict__ lo, int n4) {
    int i = blockIdx.x * blockDim.x + threadIdx.x;
    if (i >= n4) return;
    float4 v = src[i];
    __nv_bfloat16 h0 = __float2bfloat16(v.x);
    __nv_bfloat16 h1 = __float2bfloat16(v.y);
    __nv_bfloat16 h2 = __float2bfloat16(v.z);
    __nv_bfloat16 h3 = __float2bfloat16(v.w);
    hi[2 * i]     = __halves2bfloat162(h0, h1);
    hi[2 * i + 1] = __halves2bfloat162(h2, h3);
    lo[2 * i]     = __halves2bfloat162(__float2bfloat16(v.x - __bfloat162float(h0)),
                                       __float2bfloat16(v.y - __bfloat162float(h1)));
    lo[2 * i + 1] = __halves2bfloat162(__float2bfloat16(v.z - __bfloat162float(h2)),
                                       __float2bfloat16(v.w - __bfloat162float(h3)));
}

__global__ void split_w_kernel(const float* __restrict__ w0, const float* __restrict__ w1,
                               const float* __restrict__ w2, const float* __restrict__ w3,
                               __nv_bfloat162* __restrict__ hi, __nv_bfloat162* __restrict__ lo,
                               int n4) {
    int i = blockIdx.x * blockDim.x + threadIdx.x;
    if (i >= n4) return;
    const int z = blockIdx.z;
    const float* src = (z == 0) ? w0 : (z == 1) ? w1 : (z == 2) ? w2 : w3;
    float4 v = ((const float4*)src)[i];
    const size_t off = (size_t)z * n4 * 2;
    __nv_bfloat16 h0 = __float2bfloat16(v.x);
    __nv_bfloat16 h1 = __float2bfloat16(v.y);
    __nv_bfloat16 h2 = __float2bfloat16(v.z);
    __nv_bfloat16 h3 = __float2bfloat16(v.w);
    hi[off + 2 * i]     = __halves2bfloat162(h0, h1);
    hi[off + 2 * i + 1] = __halves2bfloat162(h2, h3);
    lo[off + 2 * i]     = __halves2bfloat162(__float2bfloat16(v.x - __bfloat162float(h0)),
                                             __float2bfloat16(v.y - __bfloat162float(h1)));
    lo[off + 2 * i + 1] = __halves2bfloat162(__float2bfloat16(v.z - __bfloat162float(h2)),
                                             __float2bfloat16(v.w - __bfloat162float(h3)));
}

// ---------------------------------------------------------------------------
// GEMM v4: CTA 128x128, 256 threads = 8 warps (2 M x 4 N), warp tile 64x32.
// BK=32, 2-stage, smem 80KB/CTA -> TWO CTAs resident per SM (barrier overlap).
// ---------------------------------------------------------------------------
static constexpr int GBM = 128, GBN = 128, GBK = 32;
static constexpr int LDSE = 40;                 // padded row pitch (elems)
static constexpr int ARRB = 128 * LDSE * 2;     // 10240 B per array
static constexpr int STB  = 4 * ARRB;           // 40960 B per stage
static constexpr int GSMEM = 2 * STB;           // 81920 B
static constexpr int GTH = 256;

struct GemmCore {
    __device__ static __forceinline__ void run(
        uint32_t sBase, float (&acc)[4][4][4],
        const __nv_bfloat16* gAh, const __nv_bfloat16* gAl,
        const __nv_bfloat16* gWh, const __nv_bfloat16* gWl,
        int tid, int wm, int wn, int lr, int lc)
    {
        const int cc = tid & 3;        // 16B chunk within 64B row (BK=32 bf16)
        const int rb = tid >> 2;       // 0..63
        const int NIT = ATTN_ / GBK;   // 64

        auto load_stage = [&](uint32_t st, int k0) {
#pragma unroll
            for (int bb = 0; bb < 2; bb++) {
                const int r = bb * 64 + rb;
                const uint32_t so = r * (LDSE * 2) + cc * 16;
                const size_t go = (size_t)r * ATTN_ + k0 + cc * 8;
                CP_ASYNC16(st + so,            gAh + go);
                CP_ASYNC16(st + ARRB + so,     gAl + go);
                CP_ASYNC16(st + 2 * ARRB + so, gWh + go);
                CP_ASYNC16(st + 3 * ARRB + so, gWl + go);
            }
            CP_COMMIT();
        };

        load_stage(sBase, 0);

        for (int kt = 0; kt < NIT; kt++) {
            if (kt + 1 < NIT) {
                load_stage(sBase + ((kt + 1) & 1) * STB, (kt + 1) * GBK);
                CP_WAIT(1);
            } else {
                CP_WAIT(0);
            }
            __syncthreads();

            const uint32_t st  = sBase + (kt & 1) * STB;
            const uint32_t sAh = st;
            const uint32_t sAl = st + ARRB;
            const uint32_t sWh = st + 2 * ARRB;
            const uint32_t sWl = st + 3 * ARRB;

#pragma unroll
            for (int ks = 0; ks < 2; ks++) {
                const int kc = ks * 16 + lc;
                uint32_t ah[4][4], whf[2][4], wlf[2][4];
#pragma unroll
                for (int mt = 0; mt < 4; mt++)
                    ldsm4(ah[mt], sAh + ((wm + mt * 16 + lr) * LDSE + kc) * 2);
#pragma unroll
                for (int g = 0; g < 2; g++)
                    ldsm4(whf[g], sWh + ((wn + g * 16 + lr) * LDSE + kc) * 2);
#pragma unroll
                for (int g = 0; g < 2; g++)
                    ldsm4(wlf[g], sWl + ((wn + g * 16 + lr) * LDSE + kc) * 2);

                // Ah * Wh
#pragma unroll
                for (int mt = 0; mt < 4; mt++)
#pragma unroll
                    for (int nt = 0; nt < 4; nt++)
                        mma16816(acc[mt][nt], ah[mt], whf[nt >> 1][nt & 1], whf[nt >> 1][(nt & 1) + 2]);
                // Ah * Wl
#pragma unroll
                for (int mt = 0; mt < 4; mt++)
#pragma unroll
                    for (int nt = 0; nt < 4; nt++)
                        mma16816(acc[mt][nt], ah[mt], wlf[nt >> 1][nt & 1], wlf[nt >> 1][(nt & 1) + 2]);
                // Al * Wh (reload A frags)
#pragma unroll
                for (int mt = 0; mt < 4; mt++)
                    ldsm4(ah[mt], sAl + ((wm + mt * 16 + lr) * LDSE + kc) * 2);
#pragma unroll
                for (int mt = 0; mt < 4; mt++)
#pragma unroll
                    for (int nt = 0; nt < 4; nt++)
                        mma16816(acc[mt][nt], ah[mt], whf[nt >> 1][nt & 1], whf[nt >> 1][(nt & 1) + 2]);
            }
            __syncthreads();
        }
    }
};

// ---------------------------------------------------------------------------
// Fused QKV projection GEMM. grid (48, 64). blockIdx.x>>4 : 0=Q,1=K,2=V.
// ---------------------------------------------------------------------------
__global__ void __launch_bounds__(GTH, 2) qkv_gemm(
    const __nv_bfloat16* __restrict__ Xh, const __nv_bfloat16* __restrict__ Xl,
    const __nv_bfloat16* __restrict__ Wh, const __nv_bfloat16* __restrict__ Wl,
    const float* __restrict__ bq, const float* __restrict__ bk, const float* __restrict__ bv,
    __nv_bfloat16* __restrict__ QH, __nv_bfloat16* __restrict__ QL,
    __nv_bfloat16* __restrict__ KH, __nv_bfloat16* __restrict__ KL,
    __nv_bfloat16* __restrict__ VH, __nv_bfloat16* __restrict__ VL,
    const float* __restrict__ cosT, const float* __restrict__ sinT)
{
    extern __shared__ char dsm[];
    const uint32_t sBase = smem_u32(dsm);

    const int tid  = threadIdx.x;
    const int wid  = tid >> 5;
    const int lane = tid & 31;
    const int wm   = (wid >> 2) * 64;
    const int wn   = (wid & 3) * 32;
    const int bm   = blockIdx.y * GBM;
    const int qkv  = blockIdx.x >> 4;
    const int bnl  = (blockIdx.x & 15) * GBN;
    const int bng  = blockIdx.x * GBN;

    float acc[4][4][4];
#pragma unroll
    for (int mt = 0; mt < 4; mt++)
#pragma unroll
        for (int nt = 0; nt < 4; nt++)
#pragma unroll
            for (int e = 0; e < 4; e++) acc[mt][nt][e] = 0.f;

    GemmCore::run(sBase, acc,
                  Xh + (size_t)bm * ATTN_, Xl + (size_t)bm * ATTN_,
                  Wh + (size_t)bng * ATTN_, Wl + (size_t)bng * ATTN_,
                  tid, wm, wn, lane & 15, (lane >> 4) << 3);

    const float* bias = (qkv == 0) ? bq : (qkv == 1) ? bk : bv;
    __nv_bfloat16* CH = (qkv == 0) ? QH : (qkv == 1) ? KH : VH;
    __nv_bfloat16* CL = (qkv == 0) ? QL : (qkv == 1) ? KL : VL;
    const bool rope  = (qkv != 2);
    const bool scale = (qkv == 0);
    const float qscale = 0.08838834764831843f;

    const int rr = lane >> 2;
    const int nn = (lane & 3) * 2;
#pragma unroll
    for (int mt = 0; mt < 4; mt++) {
#pragma unroll
        for (int half = 0; half < 2; half++) {
            const int m = bm + wm + mt * 16 + rr + half * 8;
            const int pos = m & (T_ - 1);
#pragma unroll
            for (int nt = 0; nt < 4; nt++) {
                const int n0 = bnl + wn + nt * 8 + nn;
                float v0 = acc[mt][nt][half * 2 + 0] + __ldg(&bias[n0]);
                float v1 = acc[mt][nt][half * 2 + 1] + __ldg(&bias[n0 + 1]);
                if (rope) {
                    const int pi = (n0 & (D_ - 1)) >> 1;
                    const float cv = __ldg(&cosT[pos * 64 + pi]);
                    const float sv = __ldg(&sinT[pos * 64 + pi]);
                    const float t1 = v0, t2 = v1;
                    v0 = t1 * cv - t2 * sv;
                    v1 = t1 * sv + t2 * cv;
                }
                if (scale) { v0 *= qscale; v1 *= qscale; }
                const __nv_bfloat16 h0 = __float2bfloat16(v0);
                const __nv_bfloat16 h1 = __float2bfloat16(v1);
                *(__nv_bfloat162*)(CH + (size_t)m * ATTN_ + n0) = __halves2bfloat162(h0, h1);
                *(__nv_bfloat162*)(CL + (size_t)m * ATTN_ + n0) = __halves2bfloat162(
                    __float2bfloat16(v0 - __bfloat162float(h0)),
                    __float2bfloat16(v1 - __bfloat162float(h1)));
            }
        }
    }
}

// ---------------------------------------------------------------------------
// Output projection GEMM: fp32 out + bias. grid (16, 64).
// ---------------------------------------------------------------------------
__global__ void __launch_bounds__(GTH, 2) out_gemm(
    const __nv_bfloat16* __restrict__ Ah, const __nv_bfloat16* __restrict__ Al,
    const __nv_bfloat16* __restrict__ Wh, const __nv_bfloat16* __restrict__ Wl,
    const float* __restrict__ bias, float* __restrict__ Cf)
{
    extern __shared__ char dsm[];
    const uint32_t sBase = smem_u32(dsm);

    const int tid  = threadIdx.x;
    const int wid  = tid >> 5;
    const int lane = tid & 31;
    const int wm   = (wid >> 2) * 64;
    const int wn   = (wid & 3) * 32;
    const int bm   = blockIdx.y * GBM;
    const int bn   = blockIdx.x * GBN;

    float acc[4][4][4];
#pragma unroll
    for (int mt = 0; mt < 4; mt++)
#pragma unroll
        for (int nt = 0; nt < 4; nt++)
#pragma unroll
            for (int e = 0; e < 4; e++) acc[mt][nt][e] = 0.f;

    GemmCore::run(sBase, acc,
                  Ah + (size_t)bm * ATTN_, Al + (size_t)bm * ATTN_,
                  Wh + (size_t)bn * ATTN_, Wl + (size_t)bn * ATTN_,
                  tid, wm, wn, lane & 15, (lane >> 4) << 3);

    const int rr = lane >> 2;
    const int nn = (lane & 3) * 2;
#pragma unroll
    for (int mt = 0; mt < 4; mt++) {
#pragma unroll
        for (int half = 0; half < 2; half++) {
            const int m = bm + wm + mt * 16 + rr + half * 8;
#pragma unroll
            for (int nt = 0; nt < 4; nt++) {
                const int n0 = bn + wn + nt * 8 + nn;
                const float v0 = acc[mt][nt][half * 2 + 0] + __ldg(&bias[n0]);
                const float v1 = acc[mt][nt][half * 2 + 1] + __ldg(&bias[n0 + 1]);
                *(float2*)(Cf + (size_t)m * ATTN_ + n0) = make_float2(v0, v1);
            }
        }
    }
}

// ---------------------------------------------------------------------------
// Tensor-core causal flash attention (unchanged, passing).
// ---------------------------------------------------------------------------
static constexpr int FLD = 136;
static constexpr int FQB = 128 * FLD * 2;
static constexpr int FKB = 64 * FLD * 2;
static constexpr int FSTG = 4 * FKB;
static constexpr int FSMEM = 2 * FQB + 2 * FSTG;

__global__ void __launch_bounds__(256, 1) flash_mma(
    const __nv_bfloat16* __restrict__ Qh, const __nv_bfloat16* __restrict__ Ql,
    const __nv_bfloat16* __restrict__ Kh, const __nv_bfloat16* __restrict__ Kl,
    const __nv_bfloat16* __restrict__ Vh, const __nv_bfloat16* __restrict__ Vl,
    __nv_bfloat16* __restrict__ Yh, __nv_bfloat16* __restrict__ Yl)
{
    extern __shared__ char fsm[];
    const uint32_t sb  = smem_u32(fsm);
    const uint32_t sQH = sb;
    const uint32_t sQL = sb + FQB;
    const uint32_t sKV = sb + 2 * FQB;

    const int qt = blockIdx.x, h = blockIdx.y, b = blockIdx.z;
    const int tid = threadIdx.x, wid = tid >> 5, lane = tid & 31;
    const int wm = wid * 16;
    const int lr = lane & 15;
    const int lcg = (lane >> 4) << 3;

    const int ccf = tid & 15;
    const int r0f = tid >> 4;

    {
        const __nv_bfloat16* qh_g = Qh + ((size_t)(b * T_ + qt * 128)) * ATTN_ + h * D_;
        const __nv_bfloat16* ql_g = Ql + ((size_t)(b * T_ + qt * 128)) * ATTN_ + h * D_;
#pragma unroll
        for (int bb = 0; bb < 8; bb++) {
            const int r = bb * 16 + r0f;
            const uint32_t so = r * (FLD * 2) + ccf * 16;
            const size_t go = (size_t)r * ATTN_ + ccf * 8;
            CP_ASYNC16(sQH + so, qh_g + go);
            CP_ASYNC16(sQL + so, ql_g + go);
        }
        CP_COMMIT();
    }

    const int nkv = 2 * qt + 2;

    auto issue_kv = [&](int j) {
        const uint32_t st = sKV + (j & 1) * FSTG;
        const size_t base = ((size_t)(b * T_ + j * 64)) * ATTN_ + h * D_;
#pragma unroll
        for (int bb = 0; bb < 4; bb++) {
            const int r = bb * 16 + r0f;
            const uint32_t so = r * (FLD * 2) + ccf * 16;
            const size_t go = base + (size_t)r * ATTN_ + ccf * 8;
            CP_ASYNC16(st + so, Kh + go);
            CP_ASYNC16(st + FKB + so, Kl + go);
            CP_ASYNC16(st + 2 * FKB + so, Vh + go);
            CP_ASYNC16(st + 3 * FKB + so, Vl + go);
        }
        CP_COMMIT();
    };

    issue_kv(0);

    float Oacc[16][4];
#pragma unroll
    for (int nt = 0; nt < 16; nt++)
#pragma unroll
        for (int e = 0; e < 4; e++) Oacc[nt][e] = 0.f;
    float m0 = -1e30f, m1 = -1e30f, l0 = 0.f, l1 = 0.f;

    const int grow0 = qt * 128 + wm + (lane >> 2);
    const int grow1 = grow0 + 8;

    for (int j = 0; j < nkv; j++) {
        if (j + 1 < nkv) {
            issue_kv(j + 1);
            CP_WAIT(1);
        } else {
            CP_WAIT(0);
        }
        __syncthreads();

        const uint32_t st  = sKV + (j & 1) * FSTG;
        const uint32_t cKH = st;
        const uint32_t cKL = st + FKB;
        const uint32_t cVH = st + 2 * FKB;
        const uint32_t cVL = st + 3 * FKB;

        float sc[8][4];
#pragma unroll
        for (int nt = 0; nt < 8; nt++)
#pragma unroll
            for (int e = 0; e < 4; e++) sc[nt][e] = 0.f;

#pragma unroll 2
        for (int ks = 0; ks < 8; ks++) {
            const int kc = ks * 16 + lcg;
            uint32_t aQh[4], aQl[4], kh[4][4], kl[4][4];
            ldsm4(aQh, sQH + ((wm + lr) * FLD + kc) * 2);
            ldsm4(aQl, sQL + ((wm + lr) * FLD + kc) * 2);
#pragma unroll
            for (int g = 0; g < 4; g++) {
                ldsm4(kh[g], cKH + ((g * 16 + lr) * FLD + kc) * 2);
                ldsm4(kl[g], cKL + ((g * 16 + lr) * FLD + kc) * 2);
            }
#pragma unroll
            for (int nt = 0; nt < 8; nt++) {
                const uint32_t b0h = kh[nt >> 1][nt & 1], b1h = kh[nt >> 1][(nt & 1) + 2];
                mma16816(sc[nt], aQh, b0h, b1h);
                mma16816(sc[nt], aQh, kl[nt >> 1][nt & 1], kl[nt >> 1][(nt & 1) + 2]);
                mma16816(sc[nt], aQl, b0h, b1h);
            }
        }

        if (j >= 2 * qt) {
            const int c0 = j * 64 + ((lane & 3) << 1);
#pragma unroll
            for (int nt = 0; nt < 8; nt++) {
                const int gc = c0 + nt * 8;
                if (gc > grow0)     sc[nt][0] = -1e30f;
                if (gc + 1 > grow0) sc[nt][1] = -1e30f;
                if (gc > grow1)     sc[nt][2] = -1e30f;
                if (gc + 1 > grow1) sc[nt][3] = -1e30f;
            }
        }
        float mx0 = -1e30f, mx1 = -1e30f;
#pragma unroll
        for (int nt = 0; nt < 8; nt++) {
            mx0 = fmaxf(mx0, fmaxf(sc[nt][0], sc[nt][1]));
            mx1 = fmaxf(mx1, fmaxf(sc[nt][2], sc[nt][3]));
        }
        mx0 = fmaxf(mx0, __shfl_xor_sync(0xffffffffu, mx0, 1));
        mx0 = fmaxf(mx0, __shfl_xor_sync(0xffffffffu, mx0, 2));
        mx1 = fmaxf(mx1, __shfl_xor_sync(0xffffffffu, mx1, 1));
        mx1 = fmaxf(mx1, __shfl_xor_sync(0xffffffffu, mx1, 2));
        const float mn0 = fmaxf(m0, mx0), mn1 = fmaxf(m1, mx1);
        const float al0 = __expf(m0 - mn0), al1 = __expf(m1 - mn1);
        float ls0 = 0.f, ls1 = 0.f;
#pragma unroll
        for (int nt = 0; nt < 8; nt++) {
            sc[nt][0] = __expf(sc[nt][0] - mn0);
            sc[nt][1] = __expf(sc[nt][1] - mn0);
            sc[nt][2] = __expf(sc[nt][2] - mn1);
            sc[nt][3] = __expf(sc[nt][3] - mn1);
            ls0 += sc[nt][0] + sc[nt][1];
            ls1 += sc[nt][2] + sc[nt][3];
        }
        ls0 += __shfl_xor_sync(0xffffffffu, ls0, 1);
        ls0 += __shfl_xor_sync(0xffffffffu, ls0, 2);
        ls1 += __shfl_xor_sync(0xffffffffu, ls1, 1);
        ls1 += __shfl_xor_sync(0xffffffffu, ls1, 2);
        l0 = l0 * al0 + ls0; m0 = mn0;
        l1 = l1 * al1 + ls1; m1 = mn1;
#pragma unroll
        for (int nt = 0; nt < 16; nt++) {
            Oacc[nt][0] *= al0; Oacc[nt][1] *= al0;
            Oacc[nt][2] *= al1; Oacc[nt][3] *= al1;
        }

#pragma unroll
        for (int ks = 0; ks < 4; ks++) {
            uint32_t aPh[4], aPl[4];
            {
                const float p0 = sc[2 * ks][0],     p1 = sc[2 * ks][1];
                const float p2 = sc[2 * ks][2],     p3 = sc[2 * ks][3];
                const float p4 = sc[2 * ks + 1][0], p5 = sc[2 * ks + 1][1];
                const float p6 = sc[2 * ks + 1][2], p7 = sc[2 * ks + 1][3];
                aPh[0] = packbf2(p0, p1);
                aPh[1] = packbf2(p2, p3);
                aPh[2] = packbf2(p4, p5);
                aPh[3] = packbf2(p6, p7);
                aPl[0] = packbf2(p0 - __bfloat162float(__float2bfloat16(p0)),
                                 p1 - __bfloat162float(__float2bfloat16(p1)));
                aPl[1] = packbf2(p2 - __bfloat162float(__float2bfloat16(p2)),
                                 p3 - __bfloat162float(__float2bfloat16(p3)));
                aPl[2] = packbf2(p4 - __bfloat162float(__float2bfloat16(p4)),
                                 p5 - __bfloat162float(__float2bfloat16(p5)));
                aPl[3] = packbf2(p6 - __bfloat162float(__float2bfloat16(p6)),
                                 p7 - __bfloat162float(__float2bfloat16(p7)));
            }
#pragma unroll
            for (int ng = 0; ng < 8; ng++) {
                uint32_t bh[4], bl[4];
                const uint32_t va = ((ks * 16 + lr) * FLD + ng * 16 + lcg) * 2;
                ldsm4t(bh, cVH + va);
                ldsm4t(bl, cVL + va);
                mma16816(Oacc[2 * ng], aPh, bh[0], bh[1]);
                mma16816(Oacc[2 * ng], aPh, bl[0], bl[1]);
                mma16816(Oacc[2 * ng], aPl, bh[0], bh[1]);
                mma16816(Oacc[2 * ng + 1], aPh, bh[2], bh[3]);
                mma16816(Oacc[2 * ng + 1], aPh, bl[2], bl[3]);
                mma16816(Oacc[2 * ng + 1], aPl, bh[2], bh[3]);
            }
        }
        __syncthreads();
    }

    const float inv0 = 1.0f / l0, inv1 = 1.0f / l1;
    const size_t rb0 = ((size_t)(b * T_) + grow0) * ATTN_ + h * D_;
    const size_t rb1 = ((size_t)(b * T_) + grow1) * ATTN_ + h * D_;
    const int nn = (lane & 3) << 1;
#pragma unroll
    for (int nt = 0; nt < 16; nt++) {
        const int col = nt * 8 + nn;
        {
            const float v0 = Oacc[nt][0] * inv0, v1 = Oacc[nt][1] * inv0;
            const __nv_bfloat16 h0 = __float2bfloat16(v0), h1 = __float2bfloat16(v1);
            *(__nv_bfloat162*)(Yh + rb0 + col) = __halves2bfloat162(h0, h1);
            *(__nv_bfloat162*)(Yl + rb0 + col) = __halves2bfloat162(
                __float2bfloat16(v0 - __bfloat162float(h0)),
                __float2bfloat16(v1 - __bfloat162float(h1)));
        }
        {
            const float v0 = Oacc[nt][2] * inv1, v1 = Oacc[nt][3] * inv1;
            const __nv_bfloat16 h0 = __float2bfloat16(v0), h1 = __float2bfloat16(v1);
            *(__nv_bfloat162*)(Yh + rb1 + col) = __halves2bfloat162(h0, h1);
            *(__nv_bfloat162*)(Yl + rb1 + col) = __halves2bfloat162(
                __float2bfloat16(v0 - __bfloat162float(h0)),
                __float2bfloat16(v1 - __bfloat162float(h1)));
        }
    }
}

// ---------------------------------------------------------------------------
// Host side. Launch order: 0 rope, 1 split_x, 2 split_w, 3 qkv, 4 flash, 5 out.
// ---------------------------------------------------------------------------
extern "C" void kernel_launch(void* const* d_in, const int* in_sizes, int n_in,
                              void* d_out, int out_size)
{
    const float* x    = (const float*)d_in[0];
    const float* wq_w = (const float*)d_in[3];
    const float* wq_b = (const float*)d_in[4];
    const float* wk_w = (const float*)d_in[5];
    const float* wk_b = (const float*)d_in[6];
    const float* wv_w = (const float*)d_in[7];
    const float* wv_b = (const float*)d_in[8];
    const float* wo_w = (const float*)d_in[9];
    const float* wo_b = (const float*)d_in[10];
    float* out = (float*)d_out;

    float *cosp, *sinp;
    __nv_bfloat16 *xh, *xl, *qh, *ql, *kh, *kl, *vh, *vl, *yh, *yl, *wh, *wl;
    cudaGetSymbolAddress((void**)&cosp, g_cosT);
    cudaGetSymbolAddress((void**)&sinp, g_sinT);
    cudaGetSymbolAddress((void**)&xh, g_xh);
    cudaGetSymbolAddress((void**)&xl, g_xl);
    cudaGetSymbolAddress((void**)&qh, g_qh);
    cudaGetSymbolAddress((void**)&ql, g_ql);
    cudaGetSymbolAddress((void**)&kh, g_kh);
    cudaGetSymbolAddress((void**)&kl, g_kl);
    cudaGetSymbolAddress((void**)&vh, g_vh);
    cudaGetSymbolAddress((void**)&vl, g_vl);
    cudaGetSymbolAddress((void**)&yh, g_yh);
    cudaGetSymbolAddress((void**)&yl, g_yl);
    cudaGetSymbolAddress((void**)&wh, g_wh);
    cudaGetSymbolAddress((void**)&wl, g_wl);

    const size_t WSZ = (size_t)ATTN_ * ATTN_;

    rope_table_kernel<<<T_, 64>>>(cosp, sinp);
    const int n4x = BT_ * ATTN_ / 4;
    split_kernel<<<n4x / 256, 256>>>((const float4*)x, (__nv_bfloat162*)xh,
                                     (__nv_bfloat162*)xl, n4x);
    const int n4w = ATTN_ * ATTN_ / 4;
    split_w_kernel<<<dim3(n4w / 256, 1, 4), 256>>>(wq_w, wk_w, wv_w, wo_w,
                                                   (__nv_bfloat162*)wh,
                                                   (__nv_bfloat162*)wl, n4w);

    cudaFuncSetAttribute(qkv_gemm, cudaFuncAttributeMaxDynamicSharedMemorySize, GSMEM);
    cudaFuncSetAttribute(out_gemm, cudaFuncAttributeMaxDynamicSharedMemorySize, GSMEM);
    cudaFuncSetAttribute(flash_mma, cudaFuncAttributeMaxDynamicSharedMemorySize, FSMEM);

    qkv_gemm<<<dim3(48, BT_ / GBM), GTH, GSMEM>>>(xh, xl, wh, wl,
                                                  wq_b, wk_b, wv_b,
                                                  qh, ql, kh, kl, vh, vl,
                                                  cosp, sinp);
    flash_mma<<<dim3(T_ / 128, H_, B_), 256, FSMEM>>>(qh, ql, kh, kl, vh, vl, yh, yl);

    out_gemm<<<dim3(ATTN_ / GBN, BT_ / GBM), GTH, GSMEM>>>(yh, yl,
                                                           wh + 3 * WSZ, wl + 3 * WSZ,
                                                           wo_b, out);
}